// round 2
// baseline (speedup 1.0000x reference)
#include <cuda_runtime.h>
#include <math.h>

#define N_NODES 100000
#define N_EDGES 1600000
#define H 64

// Scratch (device globals — no allocation allowed)
__device__ float g_deg[N_NODES];
__device__ float g_dinv[N_NODES];
__device__ float g_y[(size_t)N_NODES * H];   // x @ W for current layer
__device__ float g_a[(size_t)N_NODES * H];   // layer-1 output
__device__ float g_b2[(size_t)N_NODES * H];  // layer-2 output

__global__ void init_deg_kernel() {
    int i = blockIdx.x * blockDim.x + threadIdx.x;
    if (i < N_NODES) g_deg[i] = 1.0f;  // +1 self-loop
}

__global__ void count_deg_kernel(const int* __restrict__ ei) {
    int e = blockIdx.x * blockDim.x + threadIdx.x;
    if (e < N_EDGES) atomicAdd(&g_deg[ei[N_EDGES + e]], 1.0f);
}

__global__ void dinv_kernel() {
    int i = blockIdx.x * blockDim.x + threadIdx.x;
    if (i < N_NODES) g_dinv[i] = rsqrtf(g_deg[i]);
}

// y = x @ W ; out = y * dinv(row)^2 + b   (scatter-add target init)
// Block: 256 threads = 64 rows x 4 column-groups (16 cols each).
// xsel: 0=ext (embeddings), 1=g_a, 2=g_b2 ; osel: 0=ext (d_out), 1=g_a, 2=g_b2
__global__ void __launch_bounds__(256) gemm_kernel(
    const float* __restrict__ x_ext, const float* __restrict__ W,
    const float* __restrict__ bias, float* __restrict__ out_ext,
    int xsel, int osel)
{
    __shared__ float  xs[64][65];   // padded: kills 8-way bank conflict on xs[r][k]
    __shared__ float4 Ws[64][16];   // W row-major [k][c4]
    __shared__ float4 bs[16];

    const float* x = (xsel == 0) ? x_ext : (xsel == 1 ? g_a : g_b2);
    float* out = (osel == 0) ? out_ext : (osel == 1 ? g_a : g_b2);

    const int tid = threadIdx.x;
    const int base = blockIdx.x * 64;

    // Stage W + bias
    for (int i = tid; i < 64 * 16; i += 256)
        ((float4*)Ws)[i] = ((const float4*)W)[i];
    if (tid < 16) bs[tid] = ((const float4*)bias)[tid];

    // Stage x tile: 64 rows x 16 float4
#pragma unroll
    for (int j = 0; j < 4; j++) {
        int idx = tid + j * 256;          // [0,1024)
        int r = idx >> 4, q = idx & 15;
        if (base + r < N_NODES) {
            float4 v = ((const float4*)x)[(size_t)(base + r) * 16 + q];
            xs[r][q * 4 + 0] = v.x;
            xs[r][q * 4 + 1] = v.y;
            xs[r][q * 4 + 2] = v.z;
            xs[r][q * 4 + 3] = v.w;
        }
    }
    __syncthreads();

    const int r  = tid >> 2;        // row within tile
    const int cg = tid & 3;         // column group: 4 float4 = 16 cols
    const int row = base + r;
    if (row >= N_NODES) return;

    float4 acc[4];
#pragma unroll
    for (int c = 0; c < 4; c++) acc[c] = make_float4(0.f, 0.f, 0.f, 0.f);

#pragma unroll 8
    for (int k = 0; k < 64; k++) {
        float xk = xs[r][k];
#pragma unroll
        for (int c = 0; c < 4; c++) {
            float4 w = Ws[k][cg * 4 + c];
            acc[c].x = fmaf(xk, w.x, acc[c].x);
            acc[c].y = fmaf(xk, w.y, acc[c].y);
            acc[c].z = fmaf(xk, w.z, acc[c].z);
            acc[c].w = fmaf(xk, w.w, acc[c].w);
        }
    }

    float di = g_dinv[row];
    float s = di * di;
    float4* y4 = (float4*)g_y + (size_t)row * 16 + cg * 4;
    float4* o4 = (float4*)out + (size_t)row * 16 + cg * 4;
#pragma unroll
    for (int c = 0; c < 4; c++) {
        y4[c] = acc[c];
        float4 bv = bs[cg * 4 + c];
        float4 o;
        o.x = fmaf(acc[c].x, s, bv.x);
        o.y = fmaf(acc[c].y, s, bv.y);
        o.z = fmaf(acc[c].z, s, bv.z);
        o.w = fmaf(acc[c].w, s, bv.w);
        o4[c] = o;
    }
}

// For each edge: out[dst] += y[src] * dinv[src] * dinv[dst]
// 16 threads per edge, one red.global.add.v4.f32 (16B) each.
__global__ void __launch_bounds__(256) edge_kernel(
    const int* __restrict__ ei, float* __restrict__ out_ext, int osel)
{
    float* out = (osel == 0) ? out_ext : (osel == 1 ? g_a : g_b2);

    unsigned tid = blockIdx.x * 256u + threadIdx.x;
    unsigned e = tid >> 4;
    if (e >= N_EDGES) return;
    unsigned q = tid & 15u;

    int s = ei[e];
    int d = ei[N_EDGES + e];
    float norm = g_dinv[s] * g_dinv[d];

    float4 v = ((const float4*)g_y)[(size_t)s * 16 + q];
    v.x *= norm; v.y *= norm; v.z *= norm; v.w *= norm;

    float* addr = out + (size_t)d * 64 + q * 4;
    asm volatile("red.global.add.v4.f32 [%0], {%1,%2,%3,%4};"
                 :: "l"(addr), "f"(v.x), "f"(v.y), "f"(v.z), "f"(v.w)
                 : "memory");
}

extern "C" void kernel_launch(void* const* d_in, const int* in_sizes, int n_in,
                              void* d_out, int out_size)
{
    const float* emb = (const float*)d_in[0];
    const int*   ei  = (const int*)d_in[1];
    const float* W1  = (const float*)d_in[2];
    const float* b1  = (const float*)d_in[3];
    const float* W2  = (const float*)d_in[4];
    const float* b2  = (const float*)d_in[5];
    const float* W3  = (const float*)d_in[6];
    const float* b3  = (const float*)d_in[7];
    float* out = (float*)d_out;

    const int node_blocks = (N_NODES + 255) / 256;
    const int edge_blocks = (N_EDGES + 255) / 256;
    const int gemm_blocks = (N_NODES + 63) / 64;          // 1563
    const int ework_blocks = (N_EDGES * 16 + 255) / 256;  // 100000

    // Degree + dinv (once; shared by all 3 layers)
    init_deg_kernel<<<node_blocks, 256>>>();
    count_deg_kernel<<<edge_blocks, 256>>>(ei);
    dinv_kernel<<<node_blocks, 256>>>();

    // Layer 1: x=emb -> g_a
    gemm_kernel<<<gemm_blocks, 256>>>(emb, W1, b1, out, /*xsel=*/0, /*osel=*/1);
    edge_kernel<<<ework_blocks, 256>>>(ei, out, /*osel=*/1);

    // Layer 2: x=g_a -> g_b2
    gemm_kernel<<<gemm_blocks, 256>>>(emb, W2, b2, out, /*xsel=*/1, /*osel=*/2);
    edge_kernel<<<ework_blocks, 256>>>(ei, out, /*osel=*/2);

    // Layer 3: x=g_b2 -> d_out
    gemm_kernel<<<gemm_blocks, 256>>>(emb, W3, b3, out, /*xsel=*/2, /*osel=*/0);
    edge_kernel<<<ework_blocks, 256>>>(ei, out, /*osel=*/0);
}

// round 3
// speedup vs baseline: 1.9479x; 1.9479x over previous
#include <cuda_runtime.h>
#include <math.h>

#define N_NODES 100000
#define N_EDGES 1600000
#define H 64
#define SCAN_T 1024
#define SCAN_B ((N_NODES + SCAN_T - 1) / SCAN_T)   // 98

// Scratch (device globals — no allocation allowed)
__device__ int   g_degi[N_NODES];
__device__ float g_dinv[N_NODES];
__device__ int   g_rowptr[N_NODES + 1];
__device__ int   g_bsum[SCAN_B];
__device__ int   g_boff[SCAN_B];
__device__ int   g_cnt[N_NODES];
__device__ int   g_srcidx[N_EDGES];
__device__ float g_enorm[N_EDGES];
__device__ float g_y[(size_t)N_NODES * H];   // x @ W for current layer
__device__ float g_a[(size_t)N_NODES * H];   // layer-1 output
__device__ float g_b2[(size_t)N_NODES * H];  // layer-2 output

__global__ void zero_deg_kernel() {
    int i = blockIdx.x * blockDim.x + threadIdx.x;
    if (i < N_NODES) g_degi[i] = 0;
}

__global__ void hist_kernel(const int* __restrict__ ei) {
    int e = blockIdx.x * blockDim.x + threadIdx.x;
    if (e < N_EDGES) atomicAdd(&g_degi[ei[N_EDGES + e]], 1);
}

__global__ void dinv_kernel() {
    int i = blockIdx.x * blockDim.x + threadIdx.x;
    if (i < N_NODES) g_dinv[i] = rsqrtf((float)(g_degi[i] + 1));
}

// Block-level inclusive scan of degrees -> exclusive partials in rowptr, block sums out.
__global__ void __launch_bounds__(SCAN_T) scanA_kernel() {
    __shared__ int s[SCAN_T];
    int t = threadIdx.x;
    int i = blockIdx.x * SCAN_T + t;
    int v = (i < N_NODES) ? g_degi[i] : 0;
    s[t] = v;
    __syncthreads();
    for (int off = 1; off < SCAN_T; off <<= 1) {
        int tmp = 0;
        if (t >= off) tmp = s[t - off];
        __syncthreads();
        if (t >= off) s[t] += tmp;
        __syncthreads();
    }
    if (i < N_NODES) g_rowptr[i] = s[t] - v;  // exclusive within block
    if (t == SCAN_T - 1) g_bsum[blockIdx.x] = s[t];
}

__global__ void scanB_kernel() {
    if (threadIdx.x == 0) {
        int acc = 0;
        for (int b = 0; b < SCAN_B; b++) { g_boff[b] = acc; acc += g_bsum[b]; }
    }
}

__global__ void scanC_kernel() {
    int i = blockIdx.x * blockDim.x + threadIdx.x;
    if (i < N_NODES) {
        g_rowptr[i] += g_boff[i / SCAN_T];
        g_cnt[i] = 0;
    }
    if (i == 0) g_rowptr[N_NODES] = N_EDGES;
}

__global__ void fill_kernel(const int* __restrict__ ei) {
    int e = blockIdx.x * blockDim.x + threadIdx.x;
    if (e >= N_EDGES) return;
    int s = ei[e];
    int d = ei[N_EDGES + e];
    int p = g_rowptr[d] + atomicAdd(&g_cnt[d], 1);
    g_srcidx[p] = s;
    g_enorm[p] = g_dinv[s] * g_dinv[d];
}

// y = x @ W only (round-1 structure: 1 row/thread, 64 accumulators, W double-buffered)
// xsel: 0=ext (embeddings), 1=g_a, 2=g_b2
__global__ void __launch_bounds__(128) gemm_kernel(
    const float* __restrict__ x_ext, const float* __restrict__ W, int xsel)
{
    __shared__ float4 Ws[64][16];  // W row-major [k][c4]

    const float* x = (xsel == 0) ? x_ext : (xsel == 1 ? g_a : g_b2);

    int tid = threadIdx.x;
    for (int i = tid; i < 64 * 16; i += 128)
        ((float4*)Ws)[i] = ((const float4*)W)[i];
    __syncthreads();

    int row = blockIdx.x * 128 + tid;
    if (row >= N_NODES) return;

    const float4* x4 = (const float4*)x + (size_t)row * 16;

    float4 acc[16];
#pragma unroll
    for (int c = 0; c < 16; c++) acc[c] = make_float4(0.f, 0.f, 0.f, 0.f);

#pragma unroll 4
    for (int k4 = 0; k4 < 16; k4++) {
        float4 xv = x4[k4];
        float xs[4];
        xs[0] = xv.x; xs[1] = xv.y; xs[2] = xv.z; xs[3] = xv.w;
#pragma unroll
        for (int j = 0; j < 4; j++) {
            float xk = xs[j];
            int k = k4 * 4 + j;
#pragma unroll
            for (int c = 0; c < 16; c++) {
                float4 w = Ws[k][c];
                acc[c].x = fmaf(xk, w.x, acc[c].x);
                acc[c].y = fmaf(xk, w.y, acc[c].y);
                acc[c].z = fmaf(xk, w.z, acc[c].z);
                acc[c].w = fmaf(xk, w.w, acc[c].w);
            }
        }
    }

    float4* y4 = (float4*)g_y + (size_t)row * 16;
#pragma unroll
    for (int c = 0; c < 16; c++) y4[c] = acc[c];
}

// Pull: one warp per dst node. out[dst] = sum_{e in CSR[dst]} y[src_e]*norm_e
//                                         + y[dst]*dinv^2 + b
// Lanes: q = lane&15 (float4 column), h = lane>>4 (parallel edge slot).
__global__ void __launch_bounds__(256) pull_kernel(
    const float* __restrict__ bias, float* __restrict__ out_ext, int osel)
{
    float* out = (osel == 0) ? out_ext : (osel == 1 ? g_a : g_b2);

    int warp = (blockIdx.x * 256 + threadIdx.x) >> 5;
    if (warp >= N_NODES) return;
    int dst = warp;
    int lane = threadIdx.x & 31;
    int q = lane & 15;
    int h = lane >> 4;

    int beg = g_rowptr[dst];
    int end = g_rowptr[dst + 1];

    const float4* y4 = (const float4*)g_y;
    float4 acc = make_float4(0.f, 0.f, 0.f, 0.f);

    for (int j = beg + h; j < end; j += 2) {
        int s = g_srcidx[j];
        float nm = g_enorm[j];
        float4 v = y4[(size_t)s * 16 + q];
        acc.x = fmaf(v.x, nm, acc.x);
        acc.y = fmaf(v.y, nm, acc.y);
        acc.z = fmaf(v.z, nm, acc.z);
        acc.w = fmaf(v.w, nm, acc.w);
    }

    // combine the two edge slots
    acc.x += __shfl_xor_sync(0xFFFFFFFFu, acc.x, 16);
    acc.y += __shfl_xor_sync(0xFFFFFFFFu, acc.y, 16);
    acc.z += __shfl_xor_sync(0xFFFFFFFFu, acc.z, 16);
    acc.w += __shfl_xor_sync(0xFFFFFFFFu, acc.w, 16);

    if (h == 0) {
        float di = g_dinv[dst];
        float s2 = di * di;
        float4 ys = y4[(size_t)dst * 16 + q];
        float4 bv = ((const float4*)bias)[q];
        float4 o;
        o.x = fmaf(ys.x, s2, acc.x) + bv.x;
        o.y = fmaf(ys.y, s2, acc.y) + bv.y;
        o.z = fmaf(ys.z, s2, acc.z) + bv.z;
        o.w = fmaf(ys.w, s2, acc.w) + bv.w;
        ((float4*)out)[(size_t)dst * 16 + q] = o;
    }
}

extern "C" void kernel_launch(void* const* d_in, const int* in_sizes, int n_in,
                              void* d_out, int out_size)
{
    const float* emb = (const float*)d_in[0];
    const int*   ei  = (const int*)d_in[1];
    const float* W1  = (const float*)d_in[2];
    const float* b1  = (const float*)d_in[3];
    const float* W2  = (const float*)d_in[4];
    const float* b2  = (const float*)d_in[5];
    const float* W3  = (const float*)d_in[6];
    const float* b3  = (const float*)d_in[7];
    float* out = (float*)d_out;

    const int node_blocks = (N_NODES + 255) / 256;
    const int edge_blocks = (N_EDGES + 255) / 256;
    const int gemm_blocks = (N_NODES + 127) / 128;
    const int pull_blocks = (N_NODES + 7) / 8;   // 8 warps/block, 1 warp/node

    // ---- CSR build (once per launch) ----
    zero_deg_kernel<<<node_blocks, 256>>>();
    hist_kernel<<<edge_blocks, 256>>>(ei);
    dinv_kernel<<<node_blocks, 256>>>();
    scanA_kernel<<<SCAN_B, SCAN_T>>>();
    scanB_kernel<<<1, 32>>>();
    scanC_kernel<<<node_blocks, 256>>>();
    fill_kernel<<<edge_blocks, 256>>>(ei);

    // ---- Layer 1: emb -> g_a ----
    gemm_kernel<<<gemm_blocks, 128>>>(emb, W1, /*xsel=*/0);
    pull_kernel<<<pull_blocks, 256>>>(b1, out, /*osel=*/1);

    // ---- Layer 2: g_a -> g_b2 ----
    gemm_kernel<<<gemm_blocks, 128>>>(emb, W2, /*xsel=*/1);
    pull_kernel<<<pull_blocks, 256>>>(b2, out, /*osel=*/2);

    // ---- Layer 3: g_b2 -> d_out ----
    gemm_kernel<<<gemm_blocks, 128>>>(emb, W3, /*xsel=*/2);
    pull_kernel<<<pull_blocks, 256>>>(b3, out, /*osel=*/0);
}

// round 4
// speedup vs baseline: 2.0174x; 1.0357x over previous
#include <cuda_runtime.h>
#include <math.h>

#define N_NODES 100000
#define N_EDGES 1600000
#define H 64
#define SCAN_T 1024
#define SCAN_B ((N_NODES + SCAN_T - 1) / SCAN_T)   // 98

// Scratch (device globals — no allocation allowed)
__device__ int   g_degi[N_NODES];
__device__ float g_dinv[N_NODES];
__device__ int   g_rowptr[N_NODES + 1];
__device__ int   g_bsum[SCAN_B];
__device__ int   g_boff[SCAN_B];
__device__ int   g_cnt[N_NODES];
__device__ int   g_srcidx[N_EDGES];
__device__ float g_enorm[N_EDGES];
__device__ float g_y[(size_t)N_NODES * H];   // x @ W for current layer
__device__ float g_a[(size_t)N_NODES * H];   // layer-1 output
__device__ float g_b2[(size_t)N_NODES * H];  // layer-2 output

#define FMA2(acc, a, b) \
    asm("fma.rn.f32x2 %0, %1, %2, %0;" : "+l"(acc) : "l"(a), "l"(b))

__global__ void zero_deg_kernel() {
    int i = blockIdx.x * blockDim.x + threadIdx.x;
    if (i < N_NODES) g_degi[i] = 0;
}

__global__ void hist_kernel(const int* __restrict__ ei) {
    int e = blockIdx.x * blockDim.x + threadIdx.x;
    if (e < N_EDGES) atomicAdd(&g_degi[ei[N_EDGES + e]], 1);
}

// Block-level scan of degrees -> exclusive partials in rowptr, block sums out.
// Also computes dinv (fused).
__global__ void __launch_bounds__(SCAN_T) scanA_kernel() {
    __shared__ int s[SCAN_T];
    int t = threadIdx.x;
    int i = blockIdx.x * SCAN_T + t;
    int v = (i < N_NODES) ? g_degi[i] : 0;
    if (i < N_NODES) g_dinv[i] = rsqrtf((float)(v + 1));
    s[t] = v;
    __syncthreads();
    for (int off = 1; off < SCAN_T; off <<= 1) {
        int tmp = 0;
        if (t >= off) tmp = s[t - off];
        __syncthreads();
        if (t >= off) s[t] += tmp;
        __syncthreads();
    }
    if (i < N_NODES) g_rowptr[i] = s[t] - v;  // exclusive within block
    if (t == SCAN_T - 1) g_bsum[blockIdx.x] = s[t];
}

// Parallel exclusive scan of the 98 block sums (one 128-thread block).
__global__ void __launch_bounds__(128) scanB_kernel() {
    __shared__ int s[128];
    int t = threadIdx.x;
    int v = (t < SCAN_B) ? g_bsum[t] : 0;
    s[t] = v;
    __syncthreads();
    for (int off = 1; off < 128; off <<= 1) {
        int tmp = 0;
        if (t >= off) tmp = s[t - off];
        __syncthreads();
        if (t >= off) s[t] += tmp;
        __syncthreads();
    }
    if (t < SCAN_B) g_boff[t] = s[t] - v;  // exclusive
}

__global__ void scanC_kernel() {
    int i = blockIdx.x * blockDim.x + threadIdx.x;
    if (i < N_NODES) {
        g_rowptr[i] += g_boff[i / SCAN_T];
        g_cnt[i] = 0;
    }
    if (i == 0) g_rowptr[N_NODES] = N_EDGES;
}

__global__ void fill_kernel(const int* __restrict__ ei) {
    int e = blockIdx.x * blockDim.x + threadIdx.x;
    if (e >= N_EDGES) return;
    int s = ei[e];
    int d = ei[N_EDGES + e];
    int p = g_rowptr[d] + atomicAdd(&g_cnt[d], 1);
    g_srcidx[p] = s;
    g_enorm[p] = g_dinv[s] * g_dinv[d];
}

// y = x @ W. 1 row/thread, 64 output cols as 32 packed f32x2 accumulators.
// W broadcast from shared; FFMA2 halves the FMA instruction count.
// xsel: 0=ext (embeddings), 1=g_a, 2=g_b2
__global__ void __launch_bounds__(128, 4) gemm_kernel(
    const float* __restrict__ x_ext, const float* __restrict__ W, int xsel)
{
    __shared__ float4 Ws[64][16];  // W row-major [k][c4]

    const float* x = (xsel == 0) ? x_ext : (xsel == 1 ? g_a : g_b2);

    int tid = threadIdx.x;
    for (int i = tid; i < 64 * 16; i += 128)
        ((float4*)Ws)[i] = ((const float4*)W)[i];
    __syncthreads();

    int row = blockIdx.x * 128 + tid;
    if (row >= N_NODES) return;

    const float4* x4 = (const float4*)x + (size_t)row * 16;

    unsigned long long acc[32];
#pragma unroll
    for (int c = 0; c < 32; c++) acc[c] = 0ull;  // {0.f, 0.f}

#pragma unroll 4
    for (int k4 = 0; k4 < 16; k4++) {
        float4 xv = x4[k4];
        float xsv[4];
        xsv[0] = xv.x; xsv[1] = xv.y; xsv[2] = xv.z; xsv[3] = xv.w;
#pragma unroll
        for (int j = 0; j < 4; j++) {
            unsigned long long xk2;
            asm("mov.b64 %0, {%1, %1};" : "=l"(xk2) : "f"(xsv[j]));
            int k = k4 * 4 + j;
            const ulonglong2* wrow = (const ulonglong2*)&Ws[k][0];
#pragma unroll
            for (int c = 0; c < 16; c++) {
                ulonglong2 w = wrow[c];   // one LDS128 = 4 floats = 2 f32x2
                FMA2(acc[2 * c],     xk2, w.x);
                FMA2(acc[2 * c + 1], xk2, w.y);
            }
        }
    }

    ulonglong2* y2 = (ulonglong2*)((float4*)g_y + (size_t)row * 16);
#pragma unroll
    for (int i = 0; i < 16; i++) {
        ulonglong2 o;
        o.x = acc[2 * i];
        o.y = acc[2 * i + 1];
        y2[i] = o;
    }
}

// Pull: one warp per dst node. out[dst] = sum_{e in CSR[dst]} y[src_e]*norm_e
//                                         + y[dst]*dinv^2 + b
// Lanes: q = lane&15 (float4 column), h = lane>>4 (parallel edge slot).
__global__ void __launch_bounds__(256) pull_kernel(
    const float* __restrict__ bias, float* __restrict__ out_ext, int osel)
{
    float* out = (osel == 0) ? out_ext : (osel == 1 ? g_a : g_b2);

    int warp = (blockIdx.x * 256 + threadIdx.x) >> 5;
    if (warp >= N_NODES) return;
    int dst = warp;
    int lane = threadIdx.x & 31;
    int q = lane & 15;
    int h = lane >> 4;

    int beg = g_rowptr[dst];
    int end = g_rowptr[dst + 1];

    const float4* y4 = (const float4*)g_y;
    float4 acc = make_float4(0.f, 0.f, 0.f, 0.f);

    for (int j = beg + h; j < end; j += 2) {
        int s = g_srcidx[j];
        float nm = g_enorm[j];
        float4 v = y4[(size_t)s * 16 + q];
        acc.x = fmaf(v.x, nm, acc.x);
        acc.y = fmaf(v.y, nm, acc.y);
        acc.z = fmaf(v.z, nm, acc.z);
        acc.w = fmaf(v.w, nm, acc.w);
    }

    // combine the two edge slots
    acc.x += __shfl_xor_sync(0xFFFFFFFFu, acc.x, 16);
    acc.y += __shfl_xor_sync(0xFFFFFFFFu, acc.y, 16);
    acc.z += __shfl_xor_sync(0xFFFFFFFFu, acc.z, 16);
    acc.w += __shfl_xor_sync(0xFFFFFFFFu, acc.w, 16);

    if (h == 0) {
        float di = g_dinv[dst];
        float s2 = di * di;
        float4 ys = y4[(size_t)dst * 16 + q];
        float4 bv = ((const float4*)bias)[q];
        float4 o;
        o.x = fmaf(ys.x, s2, acc.x) + bv.x;
        o.y = fmaf(ys.y, s2, acc.y) + bv.y;
        o.z = fmaf(ys.z, s2, acc.z) + bv.z;
        o.w = fmaf(ys.w, s2, acc.w) + bv.w;
        ((float4*)out)[(size_t)dst * 16 + q] = o;
    }
}

extern "C" void kernel_launch(void* const* d_in, const int* in_sizes, int n_in,
                              void* d_out, int out_size)
{
    const float* emb = (const float*)d_in[0];
    const int*   ei  = (const int*)d_in[1];
    const float* W1  = (const float*)d_in[2];
    const float* b1  = (const float*)d_in[3];
    const float* W2  = (const float*)d_in[4];
    const float* b2  = (const float*)d_in[5];
    const float* W3  = (const float*)d_in[6];
    const float* b3  = (const float*)d_in[7];
    float* out = (float*)d_out;

    const int node_blocks = (N_NODES + 255) / 256;
    const int edge_blocks = (N_EDGES + 255) / 256;
    const int gemm_blocks = (N_NODES + 127) / 128;
    const int pull_blocks = (N_NODES + 7) / 8;   // 8 warps/block, 1 warp/node

    // ---- CSR build (once per launch) ----
    zero_deg_kernel<<<node_blocks, 256>>>();
    hist_kernel<<<edge_blocks, 256>>>(ei);
    scanA_kernel<<<SCAN_B, SCAN_T>>>();
    scanB_kernel<<<1, 128>>>();
    scanC_kernel<<<node_blocks, 256>>>();
    fill_kernel<<<edge_blocks, 256>>>(ei);

    // ---- Layer 1: emb -> g_a ----
    gemm_kernel<<<gemm_blocks, 128>>>(emb, W1, /*xsel=*/0);
    pull_kernel<<<pull_blocks, 256>>>(b1, out, /*osel=*/1);

    // ---- Layer 2: g_a -> g_b2 ----
    gemm_kernel<<<gemm_blocks, 128>>>(emb, W2, /*xsel=*/1);
    pull_kernel<<<pull_blocks, 256>>>(b2, out, /*osel=*/2);

    // ---- Layer 3: g_b2 -> d_out ----
    gemm_kernel<<<gemm_blocks, 128>>>(emb, W3, /*xsel=*/2);
    pull_kernel<<<pull_blocks, 256>>>(b3, out, /*osel=*/0);
}

// round 5
// speedup vs baseline: 2.2462x; 1.1134x over previous
#include <cuda_runtime.h>
#include <cuda_fp16.h>
#include <math.h>

#define N_NODES 100000
#define N_EDGES 1600000
#define H 64
#define SCAN_T 1024
#define SCAN_B ((N_NODES + SCAN_T - 1) / SCAN_T)   // 98

// Scratch (device globals — no allocation allowed)
__device__ int    g_degi[N_NODES];
__device__ float  g_dinv[N_NODES];
__device__ int    g_rowptr[N_NODES];       // exclusive-within-block partials
__device__ int    g_bsum[SCAN_B];
__device__ int    g_boff[SCAN_B];          // exclusive block offsets
__device__ int    g_cnt[N_NODES];
__device__ int    g_ticket;
__device__ int2   g_edge[N_EDGES];         // {src, norm-as-bits}
__device__ __half g_yh[(size_t)N_NODES * H];  // x @ W in fp16 (gather target)
__device__ float  g_a[(size_t)N_NODES * H];   // layer-1 output (fp32)
__device__ float  g_b2[(size_t)N_NODES * H];  // layer-2 output (fp32)

#define FMA2(acc, a, b) \
    asm("fma.rn.f32x2 %0, %1, %2, %0;" : "+l"(acc) : "l"(a), "l"(b))

__global__ void zero_kernel() {
    int i = blockIdx.x * blockDim.x + threadIdx.x;
    if (i < N_NODES) { g_degi[i] = 0; g_cnt[i] = 0; }
    if (i == 0) g_ticket = 0;
}

__global__ void hist_kernel(const int* __restrict__ ei) {
    int e = blockIdx.x * blockDim.x + threadIdx.x;
    if (e < N_EDGES) atomicAdd(&g_degi[ei[N_EDGES + e]], 1);
}

// Per-block scan of degrees (+ fused dinv). Last block to finish also scans
// the 98 block sums into g_boff (decoupled via ticket + threadfence).
__global__ void __launch_bounds__(SCAN_T) scanA_kernel() {
    __shared__ int s[SCAN_T];
    __shared__ int s2[128];
    __shared__ int isLast;
    int t = threadIdx.x;
    int i = blockIdx.x * SCAN_T + t;
    int v = (i < N_NODES) ? g_degi[i] : 0;
    if (i < N_NODES) g_dinv[i] = rsqrtf((float)(v + 1));
    s[t] = v;
    __syncthreads();
    for (int off = 1; off < SCAN_T; off <<= 1) {
        int tmp = 0;
        if (t >= off) tmp = s[t - off];
        __syncthreads();
        if (t >= off) s[t] += tmp;
        __syncthreads();
    }
    if (i < N_NODES) g_rowptr[i] = s[t] - v;  // exclusive within block
    if (t == SCAN_T - 1) g_bsum[blockIdx.x] = s[t];

    // ticket: last block scans the block sums
    if (t == 0) {
        __threadfence();
        int prev = atomicAdd(&g_ticket, 1);
        isLast = (prev == gridDim.x - 1) ? 1 : 0;
    }
    __syncthreads();
    if (!isLast) return;
    __threadfence();  // acquire bsum writes

    int v2 = (t < SCAN_B) ? g_bsum[t] : 0;
    if (t < 128) s2[t] = v2;
    __syncthreads();
    for (int off = 1; off < 128; off <<= 1) {
        int tmp = 0;
        if (t >= off && t < 128) tmp = s2[t - off];
        __syncthreads();
        if (t >= off && t < 128) s2[t] += tmp;
        __syncthreads();
    }
    if (t < SCAN_B) g_boff[t] = s2[t] - v2;  // exclusive
}

// CSR fill; applies g_boff on the fly (no scanC kernel).
__global__ void fill_kernel(const int* __restrict__ ei) {
    int e = blockIdx.x * blockDim.x + threadIdx.x;
    if (e >= N_EDGES) return;
    int s = ei[e];
    int d = ei[N_EDGES + e];
    int p = g_rowptr[d] + g_boff[d >> 10] + atomicAdd(&g_cnt[d], 1);
    int2 m;
    m.x = s;
    m.y = __float_as_int(g_dinv[s] * g_dinv[d]);
    g_edge[p] = m;
}

// y = x @ W. 1 row/thread, 64 cols as 32 packed f32x2 accumulators (FFMA2).
// Writes y as fp16 (half2) — halves the pull gather traffic.
// xsel: 0=ext (embeddings), 1=g_a, 2=g_b2
__global__ void __launch_bounds__(128, 4) gemm_kernel(
    const float* __restrict__ x_ext, const float* __restrict__ W, int xsel)
{
    __shared__ float4 Ws[64][16];  // W row-major [k][c4]

    const float* x = (xsel == 0) ? x_ext : (xsel == 1 ? g_a : g_b2);

    int tid = threadIdx.x;
    for (int i = tid; i < 64 * 16; i += 128)
        ((float4*)Ws)[i] = ((const float4*)W)[i];
    __syncthreads();

    int row = blockIdx.x * 128 + tid;
    if (row >= N_NODES) return;

    const float4* x4 = (const float4*)x + (size_t)row * 16;

    unsigned long long acc[32];
#pragma unroll
    for (int c = 0; c < 32; c++) acc[c] = 0ull;  // {0.f, 0.f}

#pragma unroll 4
    for (int k4 = 0; k4 < 16; k4++) {
        float4 xv = x4[k4];
        float xsv[4];
        xsv[0] = xv.x; xsv[1] = xv.y; xsv[2] = xv.z; xsv[3] = xv.w;
#pragma unroll
        for (int j = 0; j < 4; j++) {
            unsigned long long xk2;
            asm("mov.b64 %0, {%1, %1};" : "=l"(xk2) : "f"(xsv[j]));
            int k = k4 * 4 + j;
            const ulonglong2* wrow = (const ulonglong2*)&Ws[k][0];
#pragma unroll
            for (int c = 0; c < 16; c++) {
                ulonglong2 w = wrow[c];   // one LDS128 = 4 floats = 2 f32x2
                FMA2(acc[2 * c],     xk2, w.x);
                FMA2(acc[2 * c + 1], xk2, w.y);
            }
        }
    }

    // pack to fp16: acc[p] holds cols {2p, 2p+1}
    uint4* yrow = (uint4*)(g_yh + (size_t)row * H);  // 128B = 8 uint4
#pragma unroll
    for (int u = 0; u < 8; u++) {
        uint4 o;
        unsigned r[4];
#pragma unroll
        for (int j = 0; j < 4; j++) {
            float lo, hi;
            asm("mov.b64 {%0, %1}, %2;" : "=f"(lo), "=f"(hi) : "l"(acc[u * 4 + j]));
            __half2 hv = __floats2half2_rn(lo, hi);
            r[j] = *(unsigned*)&hv;
        }
        o.x = r[0]; o.y = r[1]; o.z = r[2]; o.w = r[3];
        yrow[u] = o;
    }
}

// Pull: one warp per dst. q = lane&7 (16B = 8 fp16 cols), h = lane>>3 (4 edge slots).
// out[dst] = sum_e y[src_e]*norm_e + y[dst]*dinv^2 + b   (fp32 accumulate)
__global__ void __launch_bounds__(256) pull_kernel(
    const float* __restrict__ bias, float* __restrict__ out_ext, int osel)
{
    float* out = (osel == 0) ? out_ext : (osel == 1 ? g_a : g_b2);

    int warp = (blockIdx.x * 256 + threadIdx.x) >> 5;
    if (warp >= N_NODES) return;
    int dst = warp;
    int lane = threadIdx.x & 31;
    int q = lane & 7;
    int h = lane >> 3;

    int beg = g_rowptr[dst] + g_boff[dst >> 10];
    int end = (dst + 1 < N_NODES) ? (g_rowptr[dst + 1] + g_boff[(dst + 1) >> 10])
                                  : N_EDGES;

    const uint4* y16 = (const uint4*)g_yh;  // 8 uint4 per row

    float4 a0 = make_float4(0.f, 0.f, 0.f, 0.f);
    float4 a1 = make_float4(0.f, 0.f, 0.f, 0.f);

    for (int j = beg + h; j < end; j += 4) {
        int2 m = g_edge[j];
        float nm = __int_as_float(m.y);
        uint4 v = y16[(size_t)m.x * 8 + q];
        const __half2* hp = (const __half2*)&v;
        float2 f0 = __half22float2(hp[0]);
        float2 f1 = __half22float2(hp[1]);
        float2 f2 = __half22float2(hp[2]);
        float2 f3 = __half22float2(hp[3]);
        a0.x = fmaf(f0.x, nm, a0.x); a0.y = fmaf(f0.y, nm, a0.y);
        a0.z = fmaf(f1.x, nm, a0.z); a0.w = fmaf(f1.y, nm, a0.w);
        a1.x = fmaf(f2.x, nm, a1.x); a1.y = fmaf(f2.y, nm, a1.y);
        a1.z = fmaf(f3.x, nm, a1.z); a1.w = fmaf(f3.y, nm, a1.w);
    }

    // reduce the 4 edge slots (xor over bits 3,4 of lane)
#pragma unroll
    for (int off = 8; off < 32; off <<= 1) {
        a0.x += __shfl_xor_sync(0xFFFFFFFFu, a0.x, off);
        a0.y += __shfl_xor_sync(0xFFFFFFFFu, a0.y, off);
        a0.z += __shfl_xor_sync(0xFFFFFFFFu, a0.z, off);
        a0.w += __shfl_xor_sync(0xFFFFFFFFu, a0.w, off);
        a1.x += __shfl_xor_sync(0xFFFFFFFFu, a1.x, off);
        a1.y += __shfl_xor_sync(0xFFFFFFFFu, a1.y, off);
        a1.z += __shfl_xor_sync(0xFFFFFFFFu, a1.z, off);
        a1.w += __shfl_xor_sync(0xFFFFFFFFu, a1.w, off);
    }

    if (h == 0) {
        float di = g_dinv[dst];
        float s2 = di * di;
        uint4 v = y16[(size_t)dst * 8 + q];
        const __half2* hp = (const __half2*)&v;
        float2 f0 = __half22float2(hp[0]);
        float2 f1 = __half22float2(hp[1]);
        float2 f2 = __half22float2(hp[2]);
        float2 f3 = __half22float2(hp[3]);
        float4 bv0 = ((const float4*)bias)[q * 2];
        float4 bv1 = ((const float4*)bias)[q * 2 + 1];
        float4 o0, o1;
        o0.x = fmaf(f0.x, s2, a0.x) + bv0.x;
        o0.y = fmaf(f0.y, s2, a0.y) + bv0.y;
        o0.z = fmaf(f1.x, s2, a0.z) + bv0.z;
        o0.w = fmaf(f1.y, s2, a0.w) + bv0.w;
        o1.x = fmaf(f2.x, s2, a1.x) + bv1.x;
        o1.y = fmaf(f2.y, s2, a1.y) + bv1.y;
        o1.z = fmaf(f3.x, s2, a1.z) + bv1.z;
        o1.w = fmaf(f3.y, s2, a1.w) + bv1.w;
        float4* orow = (float4*)out + (size_t)dst * 16;
        orow[q * 2]     = o0;
        orow[q * 2 + 1] = o1;
    }
}

extern "C" void kernel_launch(void* const* d_in, const int* in_sizes, int n_in,
                              void* d_out, int out_size)
{
    const float* emb = (const float*)d_in[0];
    const int*   ei  = (const int*)d_in[1];
    const float* W1  = (const float*)d_in[2];
    const float* b1  = (const float*)d_in[3];
    const float* W2  = (const float*)d_in[4];
    const float* b2  = (const float*)d_in[5];
    const float* W3  = (const float*)d_in[6];
    const float* b3  = (const float*)d_in[7];
    float* out = (float*)d_out;

    const int node_blocks = (N_NODES + 255) / 256;
    const int edge_blocks = (N_EDGES + 255) / 256;
    const int gemm_blocks = (N_NODES + 127) / 128;
    const int pull_blocks = (N_NODES + 7) / 8;   // 8 warps/block, 1 warp/node

    // ---- CSR build (once per launch) ----
    zero_kernel<<<node_blocks, 256>>>();
    hist_kernel<<<edge_blocks, 256>>>(ei);
    scanA_kernel<<<SCAN_B, SCAN_T>>>();
    fill_kernel<<<edge_blocks, 256>>>(ei);

    // ---- Layer 1: emb -> g_a ----
    gemm_kernel<<<gemm_blocks, 128>>>(emb, W1, /*xsel=*/0);
    pull_kernel<<<pull_blocks, 256>>>(b1, out, /*osel=*/1);

    // ---- Layer 2: g_a -> g_b2 ----
    gemm_kernel<<<gemm_blocks, 128>>>(emb, W2, /*xsel=*/1);
    pull_kernel<<<pull_blocks, 256>>>(b2, out, /*osel=*/2);

    // ---- Layer 3: g_b2 -> d_out ----
    gemm_kernel<<<gemm_blocks, 128>>>(emb, W3, /*xsel=*/2);
    pull_kernel<<<pull_blocks, 256>>>(b3, out, /*osel=*/0);
}